// round 8
// baseline (speedup 1.0000x reference)
#include <cuda_runtime.h>

#define WARPS_PER_BLOCK 8
#define ROWS_PER_WARP 32
#define ROWS_PER_BLOCK (WARPS_PER_BLOCK * ROWS_PER_WARP)   // 256

__device__ __forceinline__ float dot4(float4 a, float4 b) {
    return a.x*b.x + a.y*b.y + a.z*b.z + a.w*b.w;
}

// Packed reduction of 4 per-lane values across the warp. 9 SHFL total.
// PD valid on lane 0 only; PS/Q0/Q1 broadcast.
__device__ __forceinline__ void quad_reduce(float pd, float ps, float q0, float q1,
                                            int lane,
                                            float& PD, float& PS, float& Q0, float& Q1)
{
    const unsigned FULL = 0xFFFFFFFFu;
    const bool lo16 = (lane & 16) == 0;

    float a  = lo16 ? q0 : pd;
    float b  = lo16 ? q1 : ps;
    float ra = __shfl_xor_sync(FULL, a, 16);
    float rb = __shfl_xor_sync(FULL, b, 16);
    float u  = (lo16 ? pd : q0) + ra;
    float v  = (lo16 ? ps : q1) + rb;

    const bool lo8 = (lane & 8) == 0;
    float c  = lo8 ? v : u;
    float rc = __shfl_xor_sync(FULL, c, 8);
    float s  = (lo8 ? u : v) + rc;

    s += __shfl_xor_sync(FULL, s, 4);
    s += __shfl_xor_sync(FULL, s, 2);
    s += __shfl_xor_sync(FULL, s, 1);

    PD = s;                           // valid on lane 0
    PS = __shfl_sync(FULL, s, 8);
    Q0 = __shfl_sync(FULL, s, 16);
    Q1 = __shfl_sync(FULL, s, 24);
}

template <bool WRAP>
__device__ __forceinline__ void warp_body(
    const float4* __restrict__ X4, const float4* __restrict__ T4,
    const float* __restrict__ f_bias,
    float4 xi0, float4 xi1, float gb0, float gb1,
    int base, int lane, int N,
    float2* __restrict__ vfirst_slot, float2* __restrict__ obuf_w,
    float& wd_p, float& ws_p, float& v0_p, float& v1_p)
{
    auto gidx = [&](int r) -> int {
        int g = base + r;
        if (WRAP && g >= N) g -= N;
        return g;
    };

    float4 x_cur = __ldcs(X4 + (size_t)gidx(0) * 32 + lane);
    float4 t_cur = __ldcs(T4 + (size_t)gidx(0) * 32 + lane);
    float4 t_nxt = __ldcs(T4 + (size_t)gidx(1) * 32 + lane);
    float  fb_cur = __ldg(f_bias + gidx(0));

    wd_p = 0.0f; ws_p = 0.0f; v0_p = 0.0f; v1_p = 0.0f;

    #pragma unroll
    for (int r = 0; r < ROWS_PER_WARP; r++) {
        // Prefetch next iteration (distance 1); in the fast path these are
        // pure base+immediate addresses.
        float4 x_nx, t_nx2;
        if (r < ROWS_PER_WARP - 1) {
            x_nx  = __ldcs(X4 + (size_t)gidx(r + 1) * 32 + lane);
            t_nx2 = __ldcs(T4 + (size_t)gidx(r + 2) * 32 + lane);
        }
        const float fb_nxt = __ldg(f_bias + gidx(r + 1));

        float pd = dot4(x_cur, t_cur);
        float ps = dot4(x_cur, t_nxt);
        float q0 = dot4(x_cur, xi0);
        float q1 = dot4(x_cur, xi1);

        float PD, PS, Q0, Q1;
        quad_reduce(pd, ps, q0, q1, lane, PD, PS, Q0, Q1);

        const float wd = fmaxf(PD + fb_cur, 0.0f);   // lane 0 valid
        const float ws = fmaxf(PS + fb_nxt, 0.0f);
        const float v0 = fmaxf(Q0 + gb0, 0.0f);
        const float v1 = fmaxf(Q1 + gb1, 0.0f);

        if (r == 0) {
            if (lane == 0)
                *vfirst_slot = make_float2(v0, v1);
        } else if (lane == 0) {
            obuf_w[r - 1] = make_float2(wd_p * v0_p + ws_p * v0,
                                        wd_p * v1_p + ws_p * v1);
        }

        wd_p = wd; ws_p = ws; v0_p = v0; v1_p = v1;
        fb_cur = fb_nxt;
        if (r < ROWS_PER_WARP - 1) {
            x_cur = x_nx;
            t_cur = t_nxt;
            t_nxt = t_nx2;
        }
    }
}

__global__ __launch_bounds__(WARPS_PER_BLOCK * 32, 5)
void smf_kernel(const float* __restrict__ X,
                const float* __restrict__ theta,
                const float* __restrict__ f_bias,
                const float* __restrict__ xi,
                const float* __restrict__ g_bias,
                float* __restrict__ out,
                int N)
{
    __shared__ float2 Vfirst[WARPS_PER_BLOCK];
    __shared__ float2 obuf[WARPS_PER_BLOCK][ROWS_PER_WARP];

    const int warp = threadIdx.x >> 5;
    const int lane = threadIdx.x & 31;
    const int base = (blockIdx.x * WARPS_PER_BLOCK + warp) * ROWS_PER_WARP;

    const float4* __restrict__ X4  = reinterpret_cast<const float4*>(X);
    const float4* __restrict__ T4  = reinterpret_cast<const float4*>(theta);
    const float4* __restrict__ XI4 = reinterpret_cast<const float4*>(xi);

    const float4 xi0 = XI4[lane];
    const float4 xi1 = XI4[32 + lane];
    const float gb0 = g_bias[0];
    const float gb1 = g_bias[1];

    float wd_p, ws_p, v0_p, v1_p;
    if (base + ROWS_PER_WARP < N) {
        warp_body<false>(X4, T4, f_bias, xi0, xi1, gb0, gb1, base, lane, N,
                         &Vfirst[warp], obuf[warp], wd_p, ws_p, v0_p, v1_p);
    } else {
        warp_body<true>(X4, T4, f_bias, xi0, xi1, gb0, gb1, base, lane, N,
                        &Vfirst[warp], obuf[warp], wd_p, ws_p, v0_p, v1_p);
    }

    // Final row of this warp needs V[base + ROWS_PER_WARP]
    float2 vnext = make_float2(0.0f, 0.0f);
    if (warp == WARPS_PER_BLOCK - 1) {
        int h = base + ROWS_PER_WARP;
        if (h >= N) h -= N;
        const float4 xh = __ldcs(X4 + (size_t)h * 32 + lane);
        float h0 = dot4(xh, xi0);
        float h1 = dot4(xh, xi1);
        float H0, H1, D0, D1;
        quad_reduce(h0, h1, 0.0f, 0.0f, lane, H0, H1, D0, D1);
        if (lane == 0)
            vnext = make_float2(fmaxf(H0 + gb0, 0.0f), fmaxf(H1 + gb1, 0.0f));
    }
    __syncthreads();

    if (lane == 0) {
        if (warp < WARPS_PER_BLOCK - 1)
            vnext = Vfirst[warp + 1];
        obuf[warp][ROWS_PER_WARP - 1] = make_float2(wd_p * v0_p + ws_p * vnext.x,
                                                    wd_p * v1_p + ws_p * vnext.y);
    }
    __syncwarp();

    // Coalesced store: 32 lanes write the warp's 32 float2 results (256B)
    reinterpret_cast<float2*>(out)[base + lane] = obuf[warp][lane];
}

extern "C" void kernel_launch(void* const* d_in, const int* in_sizes, int n_in,
                              void* d_out, int out_size)
{
    const float* X      = (const float*)d_in[0];
    const float* theta  = (const float*)d_in[1];
    const float* f_bias = (const float*)d_in[2];
    const float* xi     = (const float*)d_in[3];
    const float* g_bias = (const float*)d_in[4];
    float* out = (float*)d_out;

    const int N = in_sizes[2];                   // f_bias has N elements
    const int blocks = N / ROWS_PER_BLOCK;       // 524288 / 256 = 2048

    smf_kernel<<<blocks, WARPS_PER_BLOCK * 32>>>(X, theta, f_bias, xi, g_bias, out, N);
}